// round 12
// baseline (speedup 1.0000x reference)
#include <cuda_runtime.h>
#include <cuda_bf16.h>
#include <cstdint>

// Problem constants
#define BB 16
#define NN 4096
#define CC 512
#define HH 8
#define DD 64
#define HWDIM 64
__device__ __constant__ float kSCALE = 0.35355339059327379f; // 64^-0.25

// ---------------------------------------------------------------------------
// Scratch (device globals; allocation inside kernel_launch is forbidden)
// ---------------------------------------------------------------------------
__device__ float g_qkv[(size_t)BB * NN * 3 * CC];            // [65536, 1536]
__device__ float g_A[(size_t)BB * HH * HWDIM * HWDIM];       // row attn  [bh,64,64]
__device__ float g_Bm[(size_t)BB * HH * HWDIM * HWDIM];      // col attn  [bh,64,64]
__device__ float g_Vt[(size_t)BB * HH * DD * HWDIM * HWDIM]; // [bh, c, t, w]
__device__ float g_attnT[(size_t)BB * CC * NN];              // [b, C, N]

// bf16 split buffers (g_Xh/g_Xl reused for attn-output before proj GEMM)
__device__ __align__(16) __nv_bfloat16 g_Xh[(size_t)BB * NN * CC];
__device__ __align__(16) __nv_bfloat16 g_Xl[(size_t)BB * NN * CC];
__device__ __align__(16) __nv_bfloat16 g_WqTh[(size_t)3 * CC * CC];
__device__ __align__(16) __nv_bfloat16 g_WqTl[(size_t)3 * CC * CC];
__device__ __align__(16) __nv_bfloat16 g_WpTh[(size_t)CC * CC];
__device__ __align__(16) __nv_bfloat16 g_WpTl[(size_t)CC * CC];

// ---------------------------------------------------------------------------
// helpers
// ---------------------------------------------------------------------------
__device__ __forceinline__ void mma16816(float* c, const uint32_t* a, const uint32_t* b)
{
    asm volatile(
        "mma.sync.aligned.m16n8k16.row.col.f32.bf16.bf16.f32 "
        "{%0,%1,%2,%3}, {%4,%5,%6,%7}, {%8,%9}, {%0,%1,%2,%3};"
        : "+f"(c[0]), "+f"(c[1]), "+f"(c[2]), "+f"(c[3])
        : "r"(a[0]), "r"(a[1]), "r"(a[2]), "r"(a[3]), "r"(b[0]), "r"(b[1]));
}
__device__ __forceinline__ uint32_t smem_u32(const void* p) {
    uint32_t a;
    asm("{ .reg .u64 t; cvta.to.shared.u64 t, %1; cvt.u32.u64 %0, t; }"
        : "=r"(a) : "l"(p));
    return a;
}
__device__ __forceinline__ void cp_async16(uint32_t dst, const void* src) {
    asm volatile("cp.async.cg.shared.global [%0], [%1], 16;" :: "r"(dst), "l"(src));
}

// ---------------------------------------------------------------------------
// fp32 -> (bf16 hi, bf16 lo) elementwise split; n4 float4 groups
// ---------------------------------------------------------------------------
__global__ __launch_bounds__(256) void split_f32(
    const float* __restrict__ in, __nv_bfloat16* __restrict__ hi,
    __nv_bfloat16* __restrict__ lo, int n4)
{
    int i = blockIdx.x * 256 + threadIdx.x;
    if (i >= n4) return;
    float4 v = ((const float4*)in)[i];
    __nv_bfloat16 h0 = __float2bfloat16(v.x);
    __nv_bfloat16 h1 = __float2bfloat16(v.y);
    __nv_bfloat16 h2 = __float2bfloat16(v.z);
    __nv_bfloat16 h3 = __float2bfloat16(v.w);
    __nv_bfloat16 l0 = __float2bfloat16(v.x - __bfloat162float(h0));
    __nv_bfloat16 l1 = __float2bfloat16(v.y - __bfloat162float(h1));
    __nv_bfloat16 l2 = __float2bfloat16(v.z - __bfloat162float(h2));
    __nv_bfloat16 l3 = __float2bfloat16(v.w - __bfloat162float(h3));
    __nv_bfloat162 hp0 = __halves2bfloat162(h0, h1);
    __nv_bfloat162 hp1 = __halves2bfloat162(h2, h3);
    __nv_bfloat162 lp0 = __halves2bfloat162(l0, l1);
    __nv_bfloat162 lp1 = __halves2bfloat162(l2, l3);
    uint2 hv, lv;
    hv.x = *(uint32_t*)&hp0; hv.y = *(uint32_t*)&hp1;
    lv.x = *(uint32_t*)&lp0; lv.y = *(uint32_t*)&lp1;
    ((uint2*)hi)[i] = hv;
    ((uint2*)lo)[i] = lv;
}

// ---------------------------------------------------------------------------
// Split + transpose weights: W[K=512][Nw] fp32 -> WT_h/WT_l [Nw][512] bf16
// ---------------------------------------------------------------------------
__global__ void split_transpose_w(
    const float* __restrict__ W, __nv_bfloat16* __restrict__ Th,
    __nv_bfloat16* __restrict__ Tl, int Nw)
{
    __shared__ float tile[32][33];
    const int n0 = blockIdx.x * 32, k0 = blockIdx.y * 32;
    const int tx = threadIdx.x, ty = threadIdx.y;
#pragma unroll
    for (int i = 0; i < 4; ++i)
        tile[ty + i * 8][tx] = W[(size_t)(k0 + ty + i * 8) * Nw + n0 + tx];
    __syncthreads();
#pragma unroll
    for (int i = 0; i < 4; ++i) {
        float v = tile[tx][ty + i * 8];
        __nv_bfloat16 h = __float2bfloat16(v);
        __nv_bfloat16 l = __float2bfloat16(v - __bfloat162float(h));
        size_t o = (size_t)(n0 + ty + i * 8) * 512 + k0 + tx;
        Th[o] = h; Tl[o] = l;
    }
}

// ---------------------------------------------------------------------------
// Split + transpose attn output: attnT[b][c][tok] fp32 -> Y[b][tok][c] bf16 h/l
// ---------------------------------------------------------------------------
__global__ void split_transpose_attn(
    const float* __restrict__ in, __nv_bfloat16* __restrict__ Yh,
    __nv_bfloat16* __restrict__ Yl)
{
    __shared__ float tile[32][33];
    const int tok0 = blockIdx.x * 32, c0 = blockIdx.y * 32, b = blockIdx.z;
    const int tx = threadIdx.x, ty = threadIdx.y;
    const float* ib = in + (size_t)b * CC * NN + (size_t)c0 * NN + tok0;
#pragma unroll
    for (int i = 0; i < 4; ++i)
        tile[ty + i * 8][tx] = ib[(size_t)(ty + i * 8) * NN + tx];
    __syncthreads();
    __nv_bfloat16* yh = Yh + (size_t)b * NN * CC;
    __nv_bfloat16* yl = Yl + (size_t)b * NN * CC;
#pragma unroll
    for (int i = 0; i < 4; ++i) {
        float v = tile[tx][ty + i * 8];
        __nv_bfloat16 h = __float2bfloat16(v);
        __nv_bfloat16 l = __float2bfloat16(v - __bfloat162float(h));
        size_t o = (size_t)(tok0 + ty + i * 8) * 512 + c0 + tx;
        yh[o] = h; yl[o] = l;
    }
}

// ---------------------------------------------------------------------------
// HMMA bf16x3-split GEMM, double-buffered cp.async + 2 CTAs/SM.
// C[M][Ntot] = (Ah+Al)[M][512] @ (Bh+Bl)^T + bias
// CTA 128x128, 8 warps (4M x 2N), warp tile 32x64, K chunks of 32 (16 chunks).
// Tiles: 128 rows x 32 bf16 at 80B row pitch. Row bases are row*20 words, so
// the 8 quad-rows of any fragment read land on distinct 4-word bank groups:
// conflict-free LDS with NO swizzle. Two 40KB buffers -> 80KB/CTA, 2 CTAs/SM.
// ---------------------------------------------------------------------------
#define SROW 80                               // bytes per smem tile row
#define TILE_B (128 * SROW)                   // 10240
#define BUF_B (4 * TILE_B)                    // 40960
#define GEMM_SMEM_BYTES (2 * BUF_B)           // 81920 -> 2 CTAs/SM

__global__ __launch_bounds__(256, 2) void gemm_bf16x3(
    const __nv_bfloat16* __restrict__ Ah, const __nv_bfloat16* __restrict__ Al,
    const __nv_bfloat16* __restrict__ BhT, const __nv_bfloat16* __restrict__ BlT,
    const float* __restrict__ bias, float* __restrict__ Cc, int Ntot)
{
    extern __shared__ __align__(16) char smem[];

    const int tid = threadIdx.x;
    const int wid = tid >> 5, lane = tid & 31;
    const int wm = wid >> 1, wn = wid & 1;       // 4 x 2 warp grid
    const int quad = lane >> 2, tq = lane & 3;
    const int boff = tq * 4;                     // byte offset within 16B chunk
    const int m0 = blockIdx.y * 128, n0 = blockIdx.x * 128;

    // staging assignment: 4 groups of 64 threads, one 128x32-bf16 tile each
    const int grp = tid >> 6;
    const int gtid = tid & 63;
    const __nv_bfloat16* src =
        (grp == 0) ? Ah + (size_t)m0 * 512 :
        (grp == 1) ? Al + (size_t)m0 * 512 :
        (grp == 2) ? BhT + (size_t)n0 * 512 :
                     BlT + (size_t)n0 * 512;
    const uint32_t dt0 = smem_u32(smem) + grp * TILE_B;   // this tile, buf0

    // prologue: stage chunk 0 into buffer 0
#pragma unroll
    for (int i = 0; i < 8; ++i) {
        int idx = gtid + 64 * i;              // 0..511
        int row = idx >> 2;                   // 0..127
        int c16 = idx & 3;                    // 16B chunk within 64B of K-data
        cp_async16(dt0 + row * SROW + c16 * 16,
                   src + (size_t)row * 512 + c16 * 8);
    }
    asm volatile("cp.async.commit_group;" ::: "memory");

    float acc[2][8][4] = {};   // [m-tile][n-tile][frag]

    for (int ch = 0; ch < 16; ++ch) {
        // issue next chunk into the other buffer, then wait for current
        if (ch < 15) {
            const __nv_bfloat16* s = src + (ch + 1) * 32;
            const uint32_t db = dt0 + ((ch + 1) & 1) * BUF_B;
#pragma unroll
            for (int i = 0; i < 8; ++i) {
                int idx = gtid + 64 * i;
                int row = idx >> 2, c16 = idx & 3;
                cp_async16(db + row * SROW + c16 * 16,
                           s + (size_t)row * 512 + c16 * 8);
            }
            asm volatile("cp.async.commit_group;" ::: "memory");
            asm volatile("cp.async.wait_group 1;" ::: "memory");
        } else {
            asm volatile("cp.async.wait_group 0;" ::: "memory");
        }
        __syncthreads();

        const char* cb = smem + (ch & 1) * BUF_B;
        const char* tAh = cb;
        const char* tAl = cb + TILE_B;
        const char* tBh = cb + 2 * TILE_B;
        const char* tBl = cb + 3 * TILE_B;
        const int ra = wm * 32;               // A row base for this warp
        const int rb = wn * 64;               // B row base for this warp

#pragma unroll
        for (int ks = 0; ks < 2; ++ks) {
            const int co0 = (2 * ks) * 16, co1 = (2 * ks + 1) * 16;
            uint32_t ah[2][4], al[2][4];
#pragma unroll
            for (int mt = 0; mt < 2; ++mt) {
                const int r0 = ra + mt * 16 + quad, r1 = r0 + 8;
                ah[mt][0] = *(const uint32_t*)(tAh + r0 * SROW + co0 + boff);
                ah[mt][1] = *(const uint32_t*)(tAh + r1 * SROW + co0 + boff);
                ah[mt][2] = *(const uint32_t*)(tAh + r0 * SROW + co1 + boff);
                ah[mt][3] = *(const uint32_t*)(tAh + r1 * SROW + co1 + boff);
                al[mt][0] = *(const uint32_t*)(tAl + r0 * SROW + co0 + boff);
                al[mt][1] = *(const uint32_t*)(tAl + r1 * SROW + co0 + boff);
                al[mt][2] = *(const uint32_t*)(tAl + r0 * SROW + co1 + boff);
                al[mt][3] = *(const uint32_t*)(tAl + r1 * SROW + co1 + boff);
            }
#pragma unroll
            for (int nt = 0; nt < 8; ++nt) {
                const int nr = rb + nt * 8 + quad;
                uint32_t bh[2], bl[2];
                bh[0] = *(const uint32_t*)(tBh + nr * SROW + co0 + boff);
                bh[1] = *(const uint32_t*)(tBh + nr * SROW + co1 + boff);
                bl[0] = *(const uint32_t*)(tBl + nr * SROW + co0 + boff);
                bl[1] = *(const uint32_t*)(tBl + nr * SROW + co1 + boff);
#pragma unroll
                for (int mt = 0; mt < 2; ++mt) {
                    mma16816(acc[mt][nt], ah[mt], bh);
                    mma16816(acc[mt][nt], ah[mt], bl);
                    mma16816(acc[mt][nt], al[mt], bh);
                }
            }
        }
        __syncthreads();   // all warps done with this buffer before restage
    }

    // epilogue: fragment layout c0,c1 -> (row, col..col+1); c2,c3 -> (row+8, ..)
#pragma unroll
    for (int mt = 0; mt < 2; ++mt) {
        const int row = m0 + wm * 32 + mt * 16 + quad;
#pragma unroll
        for (int nt = 0; nt < 8; ++nt) {
            const int col = n0 + wn * 64 + nt * 8 + tq * 2;
            const float b0 = bias[col], b1 = bias[col + 1];
            float2 v0, v1;
            v0.x = acc[mt][nt][0] + b0; v0.y = acc[mt][nt][1] + b1;
            v1.x = acc[mt][nt][2] + b0; v1.y = acc[mt][nt][3] + b1;
            *(float2*)(Cc + (size_t)row * Ntot + col) = v0;
            *(float2*)(Cc + (size_t)(row + 8) * Ntot + col) = v1;
        }
    }
}

// ---------------------------------------------------------------------------
// Axial attention logits + softmax. Row and col modes fused in one launch:
// blockIdx.y == 0 -> row attn -> outA; ==1 -> col attn -> outB.
// ---------------------------------------------------------------------------
__global__ __launch_bounds__(256) void axial_logits_softmax(
    const float* __restrict__ qkv, float* __restrict__ outA,
    float* __restrict__ outB)
{
    const int bh = blockIdx.x;
    const int colmode = blockIdx.y;
    const int b = bh >> 3, h = bh & 7;
    const float* qbase = qkv + (size_t)b * NN * (3 * CC) + h * 64;

    __shared__ float Qs[64][65];
    __shared__ float Ks[64][65];

    const int tid = threadIdx.x;
    const int tx = tid & 15;
    const int ty = tid >> 4;

    float acc[4][4] = {};

    for (int chunk = 0; chunk < 64; ++chunk) {
#pragma unroll
        for (int p = 0; p < 4; ++p) {
            int row = ty + p * 16;
            int token = colmode ? (chunk * 64 + row) : (row * 64 + chunk);
            const float* qp = qbase + (size_t)token * (3 * CC) + tx * 4;
            float4 q4 = *(const float4*)qp;
            float4 k4 = *(const float4*)(qp + CC);
            Qs[row][tx * 4 + 0] = q4.x; Qs[row][tx * 4 + 1] = q4.y;
            Qs[row][tx * 4 + 2] = q4.z; Qs[row][tx * 4 + 3] = q4.w;
            Ks[row][tx * 4 + 0] = k4.x; Ks[row][tx * 4 + 1] = k4.y;
            Ks[row][tx * 4 + 2] = k4.z; Ks[row][tx * 4 + 3] = k4.w;
        }
        __syncthreads();
#pragma unroll 16
        for (int k = 0; k < 64; ++k) {
            float qf[4], kf[4];
#pragma unroll
            for (int i = 0; i < 4; ++i) qf[i] = Qs[ty * 4 + i][k];
#pragma unroll
            for (int j = 0; j < 4; ++j) kf[j] = Ks[tx * 4 + j][k];
#pragma unroll
            for (int i = 0; i < 4; ++i)
#pragma unroll
                for (int j = 0; j < 4; ++j)
                    acc[i][j] += qf[i] * kf[j];
        }
        __syncthreads();
    }

#pragma unroll
    for (int i = 0; i < 4; ++i)
#pragma unroll
        for (int j = 0; j < 4; ++j)
            Qs[ty * 4 + i][tx * 4 + j] = acc[i][j] * kSCALE;
    __syncthreads();

    const int warp = tid >> 5, lane = tid & 31;
    float* ob = (colmode ? outB : outA) + (size_t)bh * 4096;
    for (int r = warp; r < 64; r += 8) {
        float v0 = Qs[r][lane], v1 = Qs[r][lane + 32];
        float m = fmaxf(v0, v1);
#pragma unroll
        for (int o = 16; o > 0; o >>= 1)
            m = fmaxf(m, __shfl_xor_sync(0xffffffffu, m, o));
        float e0 = __expf(v0 - m), e1 = __expf(v1 - m);
        float s = e0 + e1;
#pragma unroll
        for (int o = 16; o > 0; o >>= 1)
            s += __shfl_xor_sync(0xffffffffu, s, o);
        float inv = 1.0f / s;
        ob[r * 64 + lane] = e0 * inv;
        ob[r * 64 + lane + 32] = e1 * inv;
    }
}

// ---------------------------------------------------------------------------
// Transpose V: qkv v-part [token, h*64+c] -> Vt[bh][c][t][w]
// ---------------------------------------------------------------------------
__global__ __launch_bounds__(256) void transpose_v(
    const float* __restrict__ qkv, float* __restrict__ Vt)
{
    const int t = blockIdx.x;
    const int bh = blockIdx.y;
    const int b = bh >> 3, h = bh & 7;
    __shared__ float tile[64][65];
    const int tid = threadIdx.x;
    const int tx = tid & 15, ty = tid >> 4;

    const float* vbase = qkv + (size_t)b * NN * (3 * CC) + 2 * CC + h * 64;
#pragma unroll
    for (int p = 0; p < 4; ++p) {
        int w = ty + p * 16;
        float4 v4 = *(const float4*)(vbase + (size_t)(t * 64 + w) * (3 * CC) + tx * 4);
        tile[w][tx * 4 + 0] = v4.x; tile[w][tx * 4 + 1] = v4.y;
        tile[w][tx * 4 + 2] = v4.z; tile[w][tx * 4 + 3] = v4.w;
    }
    __syncthreads();

    float* obase = Vt + (size_t)bh * 64 * 4096 + t * 64;
#pragma unroll
    for (int p = 0; p < 4; ++p) {
        int c = ty + p * 16;
        float4 o;
        o.x = tile[tx * 4 + 0][c];
        o.y = tile[tx * 4 + 1][c];
        o.z = tile[tx * 4 + 2][c];
        o.w = tile[tx * 4 + 3][c];
        *(float4*)(obase + (size_t)c * 4096 + tx * 4) = o;
    }
}

// ---------------------------------------------------------------------------
// Coupled combine: one block per (c, bh).
// ---------------------------------------------------------------------------
__global__ __launch_bounds__(256) void combine_kernel(
    const float* __restrict__ Abuf, const float* __restrict__ Bmbuf,
    const float* __restrict__ Vt, float* __restrict__ attnT)
{
    extern __shared__ float sm[];
    float (*As_)[65] = reinterpret_cast<float (*)[65]>(sm);
    float (*Bs_)[65] = reinterpret_cast<float (*)[65]>(sm + 64 * 65);
    float (*Vs)[65]  = reinterpret_cast<float (*)[65]>(sm + 2 * 64 * 65);
    float (*Ts)[65]  = reinterpret_cast<float (*)[65]>(sm + 3 * 64 * 65);

    const int c = blockIdx.x;
    const int bh = blockIdx.y;
    const int tid = threadIdx.x;
    const int tx = tid & 15, ty = tid >> 4;

    const float* ab = Abuf + (size_t)bh * 4096;
    const float* bb = Bmbuf + (size_t)bh * 4096;
    const float* vb = Vt + ((size_t)bh * 64 + c) * 4096;

#pragma unroll
    for (int p = 0; p < 4; ++p) {
        int row = ty + p * 16;
        float4 a4 = *(const float4*)(ab + row * 64 + tx * 4);
        float4 b4 = *(const float4*)(bb + row * 64 + tx * 4);
        float4 v4 = *(const float4*)(vb + row * 64 + tx * 4);
        As_[row][tx * 4 + 0] = a4.x; As_[row][tx * 4 + 1] = a4.y;
        As_[row][tx * 4 + 2] = a4.z; As_[row][tx * 4 + 3] = a4.w;
        Bs_[row][tx * 4 + 0] = b4.x; Bs_[row][tx * 4 + 1] = b4.y;
        Bs_[row][tx * 4 + 2] = b4.z; Bs_[row][tx * 4 + 3] = b4.w;
        Vs[row][tx * 4 + 0] = v4.x; Vs[row][tx * 4 + 1] = v4.y;
        Vs[row][tx * 4 + 2] = v4.z; Vs[row][tx * 4 + 3] = v4.w;
    }
    __syncthreads();

    {
        float acc[4][4] = {};
#pragma unroll 16
        for (int w = 0; w < 64; ++w) {
            float vf[4], bf[4];
#pragma unroll
            for (int i = 0; i < 4; ++i) vf[i] = Vs[ty * 4 + i][w];
#pragma unroll
            for (int j = 0; j < 4; ++j) bf[j] = Bs_[tx * 4 + j][w];
#pragma unroll
            for (int i = 0; i < 4; ++i)
#pragma unroll
                for (int j = 0; j < 4; ++j)
                    acc[i][j] += vf[i] * bf[j];
        }
#pragma unroll
        for (int i = 0; i < 4; ++i)
#pragma unroll
            for (int j = 0; j < 4; ++j)
                Ts[ty * 4 + i][tx * 4 + j] = acc[i][j];
    }
    __syncthreads();

    float acc[4][4] = {};
#pragma unroll 16
    for (int j = 0; j < 64; ++j) {
        float af[4], tf[4];
#pragma unroll
        for (int i = 0; i < 4; ++i) af[i] = As_[ty * 4 + i][j];
#pragma unroll
        for (int jj = 0; jj < 4; ++jj) tf[jj] = Ts[j][tx * 4 + jj];
#pragma unroll
        for (int i = 0; i < 4; ++i)
#pragma unroll
            for (int jj = 0; jj < 4; ++jj)
                acc[i][jj] += af[i] * tf[jj];
    }

    float* ob = attnT + ((size_t)bh * 64 + c) * 4096;
#pragma unroll
    for (int i = 0; i < 4; ++i) {
        float4 o;
        o.x = acc[i][0]; o.y = acc[i][1]; o.z = acc[i][2]; o.w = acc[i][3];
        *(float4*)(ob + (ty * 4 + i) * 64 + tx * 4) = o;
    }
}

// ---------------------------------------------------------------------------
extern "C" void kernel_launch(void* const* d_in, const int* in_sizes, int n_in,
                              void* d_out, int out_size)
{
    const float* x     = (const float*)d_in[0];
    const float* Wqkv  = (const float*)d_in[1];
    const float* bqkv  = (const float*)d_in[2];
    const float* Wproj = (const float*)d_in[3];
    const float* bproj = (const float*)d_in[4];
    float* out = (float*)d_out;

    float *qkv, *Ab, *Bmb, *Vt, *attnT;
    __nv_bfloat16 *Xh, *Xl, *WqTh, *WqTl, *WpTh, *WpTl;
    cudaGetSymbolAddress((void**)&qkv, g_qkv);
    cudaGetSymbolAddress((void**)&Ab, g_A);
    cudaGetSymbolAddress((void**)&Bmb, g_Bm);
    cudaGetSymbolAddress((void**)&Vt, g_Vt);
    cudaGetSymbolAddress((void**)&attnT, g_attnT);
    cudaGetSymbolAddress((void**)&Xh, g_Xh);
    cudaGetSymbolAddress((void**)&Xl, g_Xl);
    cudaGetSymbolAddress((void**)&WqTh, g_WqTh);
    cudaGetSymbolAddress((void**)&WqTl, g_WqTl);
    cudaGetSymbolAddress((void**)&WpTh, g_WpTh);
    cudaGetSymbolAddress((void**)&WpTl, g_WpTl);

    // host-side attribute sets (capture-safe; proven)
    cudaFuncSetAttribute(gemm_bf16x3, cudaFuncAttributeMaxDynamicSharedMemorySize,
                         GEMM_SMEM_BYTES);
    cudaFuncSetAttribute(combine_kernel, cudaFuncAttributeMaxDynamicSharedMemorySize,
                         4 * 64 * 65 * sizeof(float));

    // 0. split inputs to bf16 hi/lo
    split_f32<<<(BB * NN * CC / 4 + 255) / 256, 256>>>(x, Xh, Xl, BB * NN * CC / 4);
    split_transpose_w<<<dim3(1536 / 32, 512 / 32), dim3(32, 8)>>>(Wqkv, WqTh, WqTl, 1536);
    split_transpose_w<<<dim3(512 / 32, 512 / 32), dim3(32, 8)>>>(Wproj, WpTh, WpTl, 512);

    // 1. QKV projection on tensor cores: [65536,512] x [512,1536]
    gemm_bf16x3<<<dim3(1536 / 128, (BB * NN) / 128), 256, GEMM_SMEM_BYTES>>>(
        Xh, Xl, WqTh, WqTl, bqkv, qkv, 1536);

    // 2+3. axial attentions (row + col fused in one launch), softmaxed
    axial_logits_softmax<<<dim3(BB * HH, 2), 256>>>(qkv, Ab, Bmb);

    // 4. transpose V to channel-major
    transpose_v<<<dim3(64, BB * HH), 256>>>(qkv, Vt);

    // 5. coupled combine -> attnT [B, C, N]
    combine_kernel<<<dim3(64, BB * HH), 256, 4 * 64 * 65 * sizeof(float)>>>(Ab, Bmb, Vt, attnT);

    // 6. split+transpose attn output to token-major bf16 (reuse Xh/Xl)
    split_transpose_attn<<<dim3(NN / 32, CC / 32, BB), dim3(32, 8)>>>(attnT, Xh, Xl);

    // 7. projection on tensor cores: [65536,512] x [512,512]
    gemm_bf16x3<<<dim3(512 / 128, (BB * NN) / 128), 256, GEMM_SMEM_BYTES>>>(
        Xh, Xl, WpTh, WpTl, bproj, out, 512);
}

// round 13
// speedup vs baseline: 1.1091x; 1.1091x over previous
#include <cuda_runtime.h>
#include <cuda_bf16.h>
#include <cstdint>

// Problem constants
#define BB 16
#define NN 4096
#define CC 512
#define HH 8
#define DD 64
#define HWDIM 64
__device__ __constant__ float kSCALE = 0.35355339059327379f; // 64^-0.25

// ---------------------------------------------------------------------------
// Scratch (device globals; allocation inside kernel_launch is forbidden)
// ---------------------------------------------------------------------------
__device__ float g_qkv[(size_t)BB * NN * 3 * CC];            // [65536, 1536]
__device__ float g_A[(size_t)BB * HH * HWDIM * HWDIM];       // row attn  [bh,64,64]
__device__ float g_Bm[(size_t)BB * HH * HWDIM * HWDIM];      // col attn  [bh,64,64]
__device__ float g_Vt[(size_t)BB * HH * DD * HWDIM * HWDIM]; // [bh, c, t, w]
__device__ float g_attnT[(size_t)BB * CC * NN];              // [b, C, N]

// bf16 split buffers (g_Xh/g_Xl reused for attn-output before proj GEMM)
__device__ __align__(16) __nv_bfloat16 g_Xh[(size_t)BB * NN * CC];
__device__ __align__(16) __nv_bfloat16 g_Xl[(size_t)BB * NN * CC];
__device__ __align__(16) __nv_bfloat16 g_WqTh[(size_t)3 * CC * CC];
__device__ __align__(16) __nv_bfloat16 g_WqTl[(size_t)3 * CC * CC];
__device__ __align__(16) __nv_bfloat16 g_WpTh[(size_t)CC * CC];
__device__ __align__(16) __nv_bfloat16 g_WpTl[(size_t)CC * CC];

// ---------------------------------------------------------------------------
// helpers
// ---------------------------------------------------------------------------
__device__ __forceinline__ void mma16816(float* c, const uint32_t* a, const uint32_t* b)
{
    asm volatile(
        "mma.sync.aligned.m16n8k16.row.col.f32.bf16.bf16.f32 "
        "{%0,%1,%2,%3}, {%4,%5,%6,%7}, {%8,%9}, {%0,%1,%2,%3};"
        : "+f"(c[0]), "+f"(c[1]), "+f"(c[2]), "+f"(c[3])
        : "r"(a[0]), "r"(a[1]), "r"(a[2]), "r"(a[3]), "r"(b[0]), "r"(b[1]));
}
__device__ __forceinline__ uint32_t smem_u32(const void* p) {
    uint32_t a;
    asm("{ .reg .u64 t; cvta.to.shared.u64 t, %1; cvt.u32.u64 %0, t; }"
        : "=r"(a) : "l"(p));
    return a;
}
__device__ __forceinline__ void cp_async16(uint32_t dst, const void* src) {
    asm volatile("cp.async.cg.shared.global [%0], [%1], 16;" :: "r"(dst), "l"(src));
}
// swizzled smem read: tile rows are 128B (8 x 16B chunks), chunk XOR (row&7)
__device__ __forceinline__ uint32_t lds_sw(const char* tile, int row, int chunk, int boff) {
    return *(const uint32_t*)(tile + row * 128 + (((chunk) ^ (row & 7)) << 4) + boff);
}

// ---------------------------------------------------------------------------
// fp32 -> (bf16 hi, bf16 lo) elementwise split; n4 float4 groups
// ---------------------------------------------------------------------------
__global__ __launch_bounds__(256) void split_f32(
    const float* __restrict__ in, __nv_bfloat16* __restrict__ hi,
    __nv_bfloat16* __restrict__ lo, int n4)
{
    int i = blockIdx.x * 256 + threadIdx.x;
    if (i >= n4) return;
    float4 v = ((const float4*)in)[i];
    __nv_bfloat16 h0 = __float2bfloat16(v.x);
    __nv_bfloat16 h1 = __float2bfloat16(v.y);
    __nv_bfloat16 h2 = __float2bfloat16(v.z);
    __nv_bfloat16 h3 = __float2bfloat16(v.w);
    __nv_bfloat16 l0 = __float2bfloat16(v.x - __bfloat162float(h0));
    __nv_bfloat16 l1 = __float2bfloat16(v.y - __bfloat162float(h1));
    __nv_bfloat16 l2 = __float2bfloat16(v.z - __bfloat162float(h2));
    __nv_bfloat16 l3 = __float2bfloat16(v.w - __bfloat162float(h3));
    __nv_bfloat162 hp0 = __halves2bfloat162(h0, h1);
    __nv_bfloat162 hp1 = __halves2bfloat162(h2, h3);
    __nv_bfloat162 lp0 = __halves2bfloat162(l0, l1);
    __nv_bfloat162 lp1 = __halves2bfloat162(l2, l3);
    uint2 hv, lv;
    hv.x = *(uint32_t*)&hp0; hv.y = *(uint32_t*)&hp1;
    lv.x = *(uint32_t*)&lp0; lv.y = *(uint32_t*)&lp1;
    ((uint2*)hi)[i] = hv;
    ((uint2*)lo)[i] = lv;
}

// ---------------------------------------------------------------------------
// Split + transpose weights: W[K=512][Nw] fp32 -> WT_h/WT_l [Nw][512] bf16
// ---------------------------------------------------------------------------
__global__ void split_transpose_w(
    const float* __restrict__ W, __nv_bfloat16* __restrict__ Th,
    __nv_bfloat16* __restrict__ Tl, int Nw)
{
    __shared__ float tile[32][33];
    const int n0 = blockIdx.x * 32, k0 = blockIdx.y * 32;
    const int tx = threadIdx.x, ty = threadIdx.y;
#pragma unroll
    for (int i = 0; i < 4; ++i)
        tile[ty + i * 8][tx] = W[(size_t)(k0 + ty + i * 8) * Nw + n0 + tx];
    __syncthreads();
#pragma unroll
    for (int i = 0; i < 4; ++i) {
        float v = tile[tx][ty + i * 8];
        __nv_bfloat16 h = __float2bfloat16(v);
        __nv_bfloat16 l = __float2bfloat16(v - __bfloat162float(h));
        size_t o = (size_t)(n0 + ty + i * 8) * 512 + k0 + tx;
        Th[o] = h; Tl[o] = l;
    }
}

// ---------------------------------------------------------------------------
// Split + transpose attn output: attnT[b][c][tok] fp32 -> Y[b][tok][c] bf16 h/l
// ---------------------------------------------------------------------------
__global__ void split_transpose_attn(
    const float* __restrict__ in, __nv_bfloat16* __restrict__ Yh,
    __nv_bfloat16* __restrict__ Yl)
{
    __shared__ float tile[32][33];
    const int tok0 = blockIdx.x * 32, c0 = blockIdx.y * 32, b = blockIdx.z;
    const int tx = threadIdx.x, ty = threadIdx.y;
    const float* ib = in + (size_t)b * CC * NN + (size_t)c0 * NN + tok0;
#pragma unroll
    for (int i = 0; i < 4; ++i)
        tile[ty + i * 8][tx] = ib[(size_t)(ty + i * 8) * NN + tx];
    __syncthreads();
    __nv_bfloat16* yh = Yh + (size_t)b * NN * CC;
    __nv_bfloat16* yl = Yl + (size_t)b * NN * CC;
#pragma unroll
    for (int i = 0; i < 4; ++i) {
        float v = tile[tx][ty + i * 8];
        __nv_bfloat16 h = __float2bfloat16(v);
        __nv_bfloat16 l = __float2bfloat16(v - __bfloat162float(h));
        size_t o = (size_t)(tok0 + ty + i * 8) * 512 + c0 + tx;
        yh[o] = h; yl[o] = l;
    }
}

// ---------------------------------------------------------------------------
// HMMA bf16x3-split GEMM: CTA tile 128(M) x 64(N), K chunks of 64, DOUBLE-
// buffered cp.async, 2 CTAs/SM (96KB smem).
// C[M][Ntot] = (Ah+Al)[M][512] @ (Bh+Bl)^T + bias
// 8 warps (4M x 2N), warp tile 32x32. XOR swizzle (proven R11) for
// conflict-free fragment LDS. Chunk count stays 8 (same barrier count as
// R11) while the load wait moves off the critical path.
// Buffer layout: [Ah 16K][Al 16K][Bh 8K][Bl 8K] = 48K; buffers at 0, 48K.
// ---------------------------------------------------------------------------
#define ATILE_B 16384                         // 128 rows * 128B
#define BTILE_B 8192                          // 64 rows * 128B
#define BUF_B (2 * ATILE_B + 2 * BTILE_B)     // 49152
#define GEMM_SMEM_BYTES (2 * BUF_B)           // 98304 -> 2 CTAs/SM

__global__ __launch_bounds__(256, 2) void gemm_bf16x3(
    const __nv_bfloat16* __restrict__ Ah, const __nv_bfloat16* __restrict__ Al,
    const __nv_bfloat16* __restrict__ BhT, const __nv_bfloat16* __restrict__ BlT,
    const float* __restrict__ bias, float* __restrict__ Cc, int Ntot)
{
    extern __shared__ __align__(16) char smem[];

    const int tid = threadIdx.x;
    const int wid = tid >> 5, lane = tid & 31;
    const int wm = wid >> 1, wn = wid & 1;       // 4 x 2 warp grid
    const int quad = lane >> 2, tq = lane & 3;
    const int boff = tq * 4;                     // byte offset within 16B chunk
    const int m0 = blockIdx.y * 128, n0 = blockIdx.x * 64;

    const uint32_t sb = smem_u32(smem);

    // staging split:
    //  A: threads 0..127 -> Ah, 128..255 -> Al; 8 chunks each (1024 per tile)
    //  B: all 256 threads -> Bh+Bl as 1024 linear chunks; 4 each
    const int agrp = tid >> 7;                   // 0: Ah, 1: Al
    const int agt = tid & 127;
    const __nv_bfloat16* asrc = (agrp ? Al : Ah) + (size_t)m0 * 512;
    const uint32_t adst = sb + agrp * ATILE_B;

    const __nv_bfloat16* bsrc0 = BhT + (size_t)n0 * 512;
    const __nv_bfloat16* bsrc1 = BlT + (size_t)n0 * 512;
    const uint32_t bdst = sb + 2 * ATILE_B;

    // ---- stage one K-chunk (k0 elements offset) into buffer at byte bufo
    auto stage = [&](int kof, uint32_t bufo) {
#pragma unroll
        for (int i = 0; i < 8; ++i) {
            int idx = agt + 128 * i;             // 0..1023
            int row = idx >> 3, c16 = idx & 7;
            cp_async16(bufo + adst + row * 128 + ((c16 ^ (row & 7)) << 4),
                       asrc + (size_t)row * 512 + kof + c16 * 8);
        }
#pragma unroll
        for (int i = 0; i < 4; ++i) {
            int idx = tid + 256 * i;             // 0..1023
            int t = idx >> 9;                    // 0: Bh, 1: Bl
            int idx2 = idx & 511;
            int row = idx2 >> 3, c16 = idx2 & 7;
            const __nv_bfloat16* s = t ? bsrc1 : bsrc0;
            cp_async16(bufo + bdst + t * BTILE_B + row * 128 + ((c16 ^ (row & 7)) << 4),
                       s + (size_t)row * 512 + kof + c16 * 8);
        }
        asm volatile("cp.async.commit_group;" ::: "memory");
    };

    // prologue: chunk 0 -> buffer 0
    stage(0, 0);

    float acc[2][4][4] = {};   // [m-tile 16r][n-tile 8c][frag]

    for (int ch = 0; ch < 8; ++ch) {
        if (ch < 7) {
            stage((ch + 1) * 64, ((ch + 1) & 1) * BUF_B);
            asm volatile("cp.async.wait_group 1;" ::: "memory");
        } else {
            asm volatile("cp.async.wait_group 0;" ::: "memory");
        }
        __syncthreads();

        const char* cb = smem + (ch & 1) * BUF_B;
        const char* tAh = cb;
        const char* tAl = cb + ATILE_B;
        const char* tBh = cb + 2 * ATILE_B;
        const char* tBl = cb + 2 * ATILE_B + BTILE_B;
        const int ra = wm * 32;               // A row base for this warp
        const int rb = wn * 32;               // B row base for this warp

#pragma unroll
        for (int ks = 0; ks < 4; ++ks) {
            const int c0_ = 2 * ks, c1_ = 2 * ks + 1;
            uint32_t ahf[2][4], alf[2][4];
#pragma unroll
            for (int mt = 0; mt < 2; ++mt) {
                const int r0 = ra + mt * 16 + quad, r1 = r0 + 8;
                ahf[mt][0] = lds_sw(tAh, r0, c0_, boff);
                ahf[mt][1] = lds_sw(tAh, r1, c0_, boff);
                ahf[mt][2] = lds_sw(tAh, r0, c1_, boff);
                ahf[mt][3] = lds_sw(tAh, r1, c1_, boff);
                alf[mt][0] = lds_sw(tAl, r0, c0_, boff);
                alf[mt][1] = lds_sw(tAl, r1, c0_, boff);
                alf[mt][2] = lds_sw(tAl, r0, c1_, boff);
                alf[mt][3] = lds_sw(tAl, r1, c1_, boff);
            }
#pragma unroll
            for (int nt = 0; nt < 4; ++nt) {
                const int nr = rb + nt * 8 + quad;
                uint32_t bh[2], bl[2];
                bh[0] = lds_sw(tBh, nr, c0_, boff);
                bh[1] = lds_sw(tBh, nr, c1_, boff);
                bl[0] = lds_sw(tBl, nr, c0_, boff);
                bl[1] = lds_sw(tBl, nr, c1_, boff);
#pragma unroll
                for (int mt = 0; mt < 2; ++mt) {
                    mma16816(acc[mt][nt], ahf[mt], bh);
                    mma16816(acc[mt][nt], ahf[mt], bl);
                    mma16816(acc[mt][nt], alf[mt], bh);
                }
            }
        }
        __syncthreads();   // all warps done with this buffer before restage
    }

    // epilogue: c0,c1 -> (row, col..col+1); c2,c3 -> (row+8, ..)
#pragma unroll
    for (int mt = 0; mt < 2; ++mt) {
        const int row = m0 + wm * 32 + mt * 16 + quad;
#pragma unroll
        for (int nt = 0; nt < 4; ++nt) {
            const int col = n0 + wn * 32 + nt * 8 + tq * 2;
            const float b0 = bias[col], b1 = bias[col + 1];
            float2 v0, v1;
            v0.x = acc[mt][nt][0] + b0; v0.y = acc[mt][nt][1] + b1;
            v1.x = acc[mt][nt][2] + b0; v1.y = acc[mt][nt][3] + b1;
            *(float2*)(Cc + (size_t)row * Ntot + col) = v0;
            *(float2*)(Cc + (size_t)(row + 8) * Ntot + col) = v1;
        }
    }
}

// ---------------------------------------------------------------------------
// Axial attention logits + softmax. Row and col modes fused in one launch:
// blockIdx.y == 0 -> row attn -> outA; ==1 -> col attn -> outB.
// ---------------------------------------------------------------------------
__global__ __launch_bounds__(256) void axial_logits_softmax(
    const float* __restrict__ qkv, float* __restrict__ outA,
    float* __restrict__ outB)
{
    const int bh = blockIdx.x;
    const int colmode = blockIdx.y;
    const int b = bh >> 3, h = bh & 7;
    const float* qbase = qkv + (size_t)b * NN * (3 * CC) + h * 64;

    __shared__ float Qs[64][65];
    __shared__ float Ks[64][65];

    const int tid = threadIdx.x;
    const int tx = tid & 15;
    const int ty = tid >> 4;

    float acc[4][4] = {};

    for (int chunk = 0; chunk < 64; ++chunk) {
#pragma unroll
        for (int p = 0; p < 4; ++p) {
            int row = ty + p * 16;
            int token = colmode ? (chunk * 64 + row) : (row * 64 + chunk);
            const float* qp = qbase + (size_t)token * (3 * CC) + tx * 4;
            float4 q4 = *(const float4*)qp;
            float4 k4 = *(const float4*)(qp + CC);
            Qs[row][tx * 4 + 0] = q4.x; Qs[row][tx * 4 + 1] = q4.y;
            Qs[row][tx * 4 + 2] = q4.z; Qs[row][tx * 4 + 3] = q4.w;
            Ks[row][tx * 4 + 0] = k4.x; Ks[row][tx * 4 + 1] = k4.y;
            Ks[row][tx * 4 + 2] = k4.z; Ks[row][tx * 4 + 3] = k4.w;
        }
        __syncthreads();
#pragma unroll 16
        for (int k = 0; k < 64; ++k) {
            float qf[4], kf[4];
#pragma unroll
            for (int i = 0; i < 4; ++i) qf[i] = Qs[ty * 4 + i][k];
#pragma unroll
            for (int j = 0; j < 4; ++j) kf[j] = Ks[tx * 4 + j][k];
#pragma unroll
            for (int i = 0; i < 4; ++i)
#pragma unroll
                for (int j = 0; j < 4; ++j)
                    acc[i][j] += qf[i] * kf[j];
        }
        __syncthreads();
    }

#pragma unroll
    for (int i = 0; i < 4; ++i)
#pragma unroll
        for (int j = 0; j < 4; ++j)
            Qs[ty * 4 + i][tx * 4 + j] = acc[i][j] * kSCALE;
    __syncthreads();

    const int warp = tid >> 5, lane = tid & 31;
    float* ob = (colmode ? outB : outA) + (size_t)bh * 4096;
    for (int r = warp; r < 64; r += 8) {
        float v0 = Qs[r][lane], v1 = Qs[r][lane + 32];
        float m = fmaxf(v0, v1);
#pragma unroll
        for (int o = 16; o > 0; o >>= 1)
            m = fmaxf(m, __shfl_xor_sync(0xffffffffu, m, o));
        float e0 = __expf(v0 - m), e1 = __expf(v1 - m);
        float s = e0 + e1;
#pragma unroll
        for (int o = 16; o > 0; o >>= 1)
            s += __shfl_xor_sync(0xffffffffu, s, o);
        float inv = 1.0f / s;
        ob[r * 64 + lane] = e0 * inv;
        ob[r * 64 + lane + 32] = e1 * inv;
    }
}

// ---------------------------------------------------------------------------
// Transpose V: qkv v-part [token, h*64+c] -> Vt[bh][c][t][w]
// ---------------------------------------------------------------------------
__global__ __launch_bounds__(256) void transpose_v(
    const float* __restrict__ qkv, float* __restrict__ Vt)
{
    const int t = blockIdx.x;
    const int bh = blockIdx.y;
    const int b = bh >> 3, h = bh & 7;
    __shared__ float tile[64][65];
    const int tid = threadIdx.x;
    const int tx = tid & 15, ty = tid >> 4;

    const float* vbase = qkv + (size_t)b * NN * (3 * CC) + 2 * CC + h * 64;
#pragma unroll
    for (int p = 0; p < 4; ++p) {
        int w = ty + p * 16;
        float4 v4 = *(const float4*)(vbase + (size_t)(t * 64 + w) * (3 * CC) + tx * 4);
        tile[w][tx * 4 + 0] = v4.x; tile[w][tx * 4 + 1] = v4.y;
        tile[w][tx * 4 + 2] = v4.z; tile[w][tx * 4 + 3] = v4.w;
    }
    __syncthreads();

    float* obase = Vt + (size_t)bh * 64 * 4096 + t * 64;
#pragma unroll
    for (int p = 0; p < 4; ++p) {
        int c = ty + p * 16;
        float4 o;
        o.x = tile[tx * 4 + 0][c];
        o.y = tile[tx * 4 + 1][c];
        o.z = tile[tx * 4 + 2][c];
        o.w = tile[tx * 4 + 3][c];
        *(float4*)(obase + (size_t)c * 4096 + tx * 4) = o;
    }
}

// ---------------------------------------------------------------------------
// Coupled combine: one block per (c, bh).
// ---------------------------------------------------------------------------
__global__ __launch_bounds__(256) void combine_kernel(
    const float* __restrict__ Abuf, const float* __restrict__ Bmbuf,
    const float* __restrict__ Vt, float* __restrict__ attnT)
{
    extern __shared__ float sm[];
    float (*As_)[65] = reinterpret_cast<float (*)[65]>(sm);
    float (*Bs_)[65] = reinterpret_cast<float (*)[65]>(sm + 64 * 65);
    float (*Vs)[65]  = reinterpret_cast<float (*)[65]>(sm + 2 * 64 * 65);
    float (*Ts)[65]  = reinterpret_cast<float (*)[65]>(sm + 3 * 64 * 65);

    const int c = blockIdx.x;
    const int bh = blockIdx.y;
    const int tid = threadIdx.x;
    const int tx = tid & 15, ty = tid >> 4;

    const float* ab = Abuf + (size_t)bh * 4096;
    const float* bb = Bmbuf + (size_t)bh * 4096;
    const float* vb = Vt + ((size_t)bh * 64 + c) * 4096;

#pragma unroll
    for (int p = 0; p < 4; ++p) {
        int row = ty + p * 16;
        float4 a4 = *(const float4*)(ab + row * 64 + tx * 4);
        float4 b4 = *(const float4*)(bb + row * 64 + tx * 4);
        float4 v4 = *(const float4*)(vb + row * 64 + tx * 4);
        As_[row][tx * 4 + 0] = a4.x; As_[row][tx * 4 + 1] = a4.y;
        As_[row][tx * 4 + 2] = a4.z; As_[row][tx * 4 + 3] = a4.w;
        Bs_[row][tx * 4 + 0] = b4.x; Bs_[row][tx * 4 + 1] = b4.y;
        Bs_[row][tx * 4 + 2] = b4.z; Bs_[row][tx * 4 + 3] = b4.w;
        Vs[row][tx * 4 + 0] = v4.x; Vs[row][tx * 4 + 1] = v4.y;
        Vs[row][tx * 4 + 2] = v4.z; Vs[row][tx * 4 + 3] = v4.w;
    }
    __syncthreads();

    {
        float acc[4][4] = {};
#pragma unroll 16
        for (int w = 0; w < 64; ++w) {
            float vf[4], bf[4];
#pragma unroll
            for (int i = 0; i < 4; ++i) vf[i] = Vs[ty * 4 + i][w];
#pragma unroll
            for (int j = 0; j < 4; ++j) bf[j] = Bs_[tx * 4 + j][w];
#pragma unroll
            for (int i = 0; i < 4; ++i)
#pragma unroll
                for (int j = 0; j < 4; ++j)
                    acc[i][j] += vf[i] * bf[j];
        }
#pragma unroll
        for (int i = 0; i < 4; ++i)
#pragma unroll
            for (int j = 0; j < 4; ++j)
                Ts[ty * 4 + i][tx * 4 + j] = acc[i][j];
    }
    __syncthreads();

    float acc[4][4] = {};
#pragma unroll 16
    for (int j = 0; j < 64; ++j) {
        float af[4], tf[4];
#pragma unroll
        for (int i = 0; i < 4; ++i) af[i] = As_[ty * 4 + i][j];
#pragma unroll
        for (int jj = 0; jj < 4; ++jj) tf[jj] = Ts[j][tx * 4 + jj];
#pragma unroll
        for (int i = 0; i < 4; ++i)
#pragma unroll
            for (int jj = 0; jj < 4; ++jj)
                acc[i][jj] += af[i] * tf[jj];
    }

    float* ob = attnT + ((size_t)bh * 64 + c) * 4096;
#pragma unroll
    for (int i = 0; i < 4; ++i) {
        float4 o;
        o.x = acc[i][0]; o.y = acc[i][1]; o.z = acc[i][2]; o.w = acc[i][3];
        *(float4*)(ob + (ty * 4 + i) * 64 + tx * 4) = o;
    }
}

// ---------------------------------------------------------------------------
extern "C" void kernel_launch(void* const* d_in, const int* in_sizes, int n_in,
                              void* d_out, int out_size)
{
    const float* x     = (const float*)d_in[0];
    const float* Wqkv  = (const float*)d_in[1];
    const float* bqkv  = (const float*)d_in[2];
    const float* Wproj = (const float*)d_in[3];
    const float* bproj = (const float*)d_in[4];
    float* out = (float*)d_out;

    float *qkv, *Ab, *Bmb, *Vt, *attnT;
    __nv_bfloat16 *Xh, *Xl, *WqTh, *WqTl, *WpTh, *WpTl;
    cudaGetSymbolAddress((void**)&qkv, g_qkv);
    cudaGetSymbolAddress((void**)&Ab, g_A);
    cudaGetSymbolAddress((void**)&Bmb, g_Bm);
    cudaGetSymbolAddress((void**)&Vt, g_Vt);
    cudaGetSymbolAddress((void**)&attnT, g_attnT);
    cudaGetSymbolAddress((void**)&Xh, g_Xh);
    cudaGetSymbolAddress((void**)&Xl, g_Xl);
    cudaGetSymbolAddress((void**)&WqTh, g_WqTh);
    cudaGetSymbolAddress((void**)&WqTl, g_WqTl);
    cudaGetSymbolAddress((void**)&WpTh, g_WpTh);
    cudaGetSymbolAddress((void**)&WpTl, g_WpTl);

    // host-side attribute sets (capture-safe; proven)
    cudaFuncSetAttribute(gemm_bf16x3, cudaFuncAttributeMaxDynamicSharedMemorySize,
                         GEMM_SMEM_BYTES);
    cudaFuncSetAttribute(combine_kernel, cudaFuncAttributeMaxDynamicSharedMemorySize,
                         4 * 64 * 65 * sizeof(float));

    // 0. split inputs to bf16 hi/lo
    split_f32<<<(BB * NN * CC / 4 + 255) / 256, 256>>>(x, Xh, Xl, BB * NN * CC / 4);
    split_transpose_w<<<dim3(1536 / 32, 512 / 32), dim3(32, 8)>>>(Wqkv, WqTh, WqTl, 1536);
    split_transpose_w<<<dim3(512 / 32, 512 / 32), dim3(32, 8)>>>(Wproj, WpTh, WpTl, 512);

    // 1. QKV projection on tensor cores: [65536,512] x [512,1536]
    gemm_bf16x3<<<dim3(1536 / 64, (BB * NN) / 128), 256, GEMM_SMEM_BYTES>>>(
        Xh, Xl, WqTh, WqTl, bqkv, qkv, 1536);

    // 2+3. axial attentions (row + col fused in one launch), softmaxed
    axial_logits_softmax<<<dim3(BB * HH, 2), 256>>>(qkv, Ab, Bmb);

    // 4. transpose V to channel-major
    transpose_v<<<dim3(64, BB * HH), 256>>>(qkv, Vt);

    // 5. coupled combine -> attnT [B, C, N]
    combine_kernel<<<dim3(64, BB * HH), 256, 4 * 64 * 65 * sizeof(float)>>>(Ab, Bmb, Vt, attnT);

    // 6. split+transpose attn output to token-major bf16 (reuse Xh/Xl)
    split_transpose_attn<<<dim3(NN / 32, CC / 32, BB), dim3(32, 8)>>>(attnT, Xh, Xl);

    // 7. projection on tensor cores: [65536,512] x [512,512]
    gemm_bf16x3<<<dim3(512 / 64, (BB * NN) / 128), 256, GEMM_SMEM_BYTES>>>(
        Xh, Xl, WpTh, WpTl, bproj, out, 512);
}

// round 17
// speedup vs baseline: 1.3779x; 1.2424x over previous
#include <cuda_runtime.h>
#include <cuda_bf16.h>
#include <cstdint>

// Problem constants
#define BB 16
#define NN 4096
#define CC 512
#define HH 8
#define DD 64
#define HWDIM 64
__device__ __constant__ float kSCALE = 0.35355339059327379f; // 64^-0.25

// ---------------------------------------------------------------------------
// Scratch (device globals; allocation inside kernel_launch is forbidden)
// ---------------------------------------------------------------------------
__device__ float g_qkv[(size_t)BB * NN * 3 * CC];            // [65536, 1536]
__device__ float g_A[(size_t)BB * HH * HWDIM * HWDIM];       // row attn  [bh,64,64]
__device__ float g_Bm[(size_t)BB * HH * HWDIM * HWDIM];      // col attn  [bh,64,64]
__device__ float g_Vt[(size_t)BB * HH * DD * HWDIM * HWDIM]; // [bh, c, t, w]
__device__ float g_attnT[(size_t)BB * CC * NN];              // [b, C, N]

// bf16 split buffers (g_Xh/g_Xl reused for attn-output before proj GEMM)
__device__ __align__(16) __nv_bfloat16 g_Xh[(size_t)BB * NN * CC];
__device__ __align__(16) __nv_bfloat16 g_Xl[(size_t)BB * NN * CC];
__device__ __align__(16) __nv_bfloat16 g_WqTh[(size_t)3 * CC * CC];
__device__ __align__(16) __nv_bfloat16 g_WqTl[(size_t)3 * CC * CC];
__device__ __align__(16) __nv_bfloat16 g_WpTh[(size_t)CC * CC];
__device__ __align__(16) __nv_bfloat16 g_WpTl[(size_t)CC * CC];

// ---------------------------------------------------------------------------
// helpers
// ---------------------------------------------------------------------------
__device__ __forceinline__ void mma16816(float* c, const uint32_t* a, const uint32_t* b)
{
    asm volatile(
        "mma.sync.aligned.m16n8k16.row.col.f32.bf16.bf16.f32 "
        "{%0,%1,%2,%3}, {%4,%5,%6,%7}, {%8,%9}, {%0,%1,%2,%3};"
        : "+f"(c[0]), "+f"(c[1]), "+f"(c[2]), "+f"(c[3])
        : "r"(a[0]), "r"(a[1]), "r"(a[2]), "r"(a[3]), "r"(b[0]), "r"(b[1]));
}
__device__ __forceinline__ uint32_t smem_u32(const void* p) {
    uint32_t a;
    asm("{ .reg .u64 t; cvta.to.shared.u64 t, %1; cvt.u32.u64 %0, t; }"
        : "=r"(a) : "l"(p));
    return a;
}
__device__ __forceinline__ void cp_async16(uint32_t dst, const void* src) {
    asm volatile("cp.async.cg.shared.global [%0], [%1], 16;" :: "r"(dst), "l"(src));
}
// swizzled smem read: tile rows are 128B (8 x 16B chunks), chunk XOR (row&7)
__device__ __forceinline__ uint32_t lds_sw(const char* tile, int row, int chunk, int boff) {
    return *(const uint32_t*)(tile + row * 128 + (((chunk) ^ (row & 7)) << 4) + boff);
}
// split float4 -> packed bf16x2 pairs (hi and lo residual)
__device__ __forceinline__ void split4(float4 v, uint2& h, uint2& l) {
    __nv_bfloat16 h0 = __float2bfloat16(v.x);
    __nv_bfloat16 h1 = __float2bfloat16(v.y);
    __nv_bfloat16 h2 = __float2bfloat16(v.z);
    __nv_bfloat16 h3 = __float2bfloat16(v.w);
    __nv_bfloat16 l0 = __float2bfloat16(v.x - __bfloat162float(h0));
    __nv_bfloat16 l1 = __float2bfloat16(v.y - __bfloat162float(h1));
    __nv_bfloat16 l2 = __float2bfloat16(v.z - __bfloat162float(h2));
    __nv_bfloat16 l3 = __float2bfloat16(v.w - __bfloat162float(h3));
    __nv_bfloat162 hp0 = __halves2bfloat162(h0, h1);
    __nv_bfloat162 hp1 = __halves2bfloat162(h2, h3);
    __nv_bfloat162 lp0 = __halves2bfloat162(l0, l1);
    __nv_bfloat162 lp1 = __halves2bfloat162(l2, l3);
    h.x = *(uint32_t*)&hp0; h.y = *(uint32_t*)&hp1;
    l.x = *(uint32_t*)&lp0; l.y = *(uint32_t*)&lp1;
}

// ---------------------------------------------------------------------------
// fp32 -> (bf16 hi, bf16 lo) elementwise split; n4 float4 groups
// ---------------------------------------------------------------------------
__global__ __launch_bounds__(256) void split_f32(
    const float* __restrict__ in, __nv_bfloat16* __restrict__ hi,
    __nv_bfloat16* __restrict__ lo, int n4)
{
    int i = blockIdx.x * 256 + threadIdx.x;
    if (i >= n4) return;
    float4 v = ((const float4*)in)[i];
    uint2 hv, lv;
    split4(v, hv, lv);
    ((uint2*)hi)[i] = hv;
    ((uint2*)lo)[i] = lv;
}

// ---------------------------------------------------------------------------
// Split + transpose weights: W[K=512][Nw] fp32 -> WT_h/WT_l [Nw][512] bf16
// ---------------------------------------------------------------------------
__global__ void split_transpose_w(
    const float* __restrict__ W, __nv_bfloat16* __restrict__ Th,
    __nv_bfloat16* __restrict__ Tl, int Nw)
{
    __shared__ float tile[32][33];
    const int n0 = blockIdx.x * 32, k0 = blockIdx.y * 32;
    const int tx = threadIdx.x, ty = threadIdx.y;
#pragma unroll
    for (int i = 0; i < 4; ++i)
        tile[ty + i * 8][tx] = W[(size_t)(k0 + ty + i * 8) * Nw + n0 + tx];
    __syncthreads();
#pragma unroll
    for (int i = 0; i < 4; ++i) {
        float v = tile[tx][ty + i * 8];
        __nv_bfloat16 h = __float2bfloat16(v);
        __nv_bfloat16 l = __float2bfloat16(v - __bfloat162float(h));
        size_t o = (size_t)(n0 + ty + i * 8) * 512 + k0 + tx;
        Th[o] = h; Tl[o] = l;
    }
}

// ---------------------------------------------------------------------------
// Split + transpose attn output: attnT[b][c][tok] fp32 -> Y[b][tok][c] bf16 h/l
// ---------------------------------------------------------------------------
__global__ void split_transpose_attn(
    const float* __restrict__ in, __nv_bfloat16* __restrict__ Yh,
    __nv_bfloat16* __restrict__ Yl)
{
    __shared__ float tile[32][33];
    const int tok0 = blockIdx.x * 32, c0 = blockIdx.y * 32, b = blockIdx.z;
    const int tx = threadIdx.x, ty = threadIdx.y;
    const float* ib = in + (size_t)b * CC * NN + (size_t)c0 * NN + tok0;
#pragma unroll
    for (int i = 0; i < 4; ++i)
        tile[ty + i * 8][tx] = ib[(size_t)(ty + i * 8) * NN + tx];
    __syncthreads();
    __nv_bfloat16* yh = Yh + (size_t)b * NN * CC;
    __nv_bfloat16* yl = Yl + (size_t)b * NN * CC;
#pragma unroll
    for (int i = 0; i < 4; ++i) {
        float v = tile[tx][ty + i * 8];
        __nv_bfloat16 h = __float2bfloat16(v);
        __nv_bfloat16 l = __float2bfloat16(v - __bfloat162float(h));
        size_t o = (size_t)(tok0 + ty + i * 8) * 512 + c0 + tx;
        yh[o] = h; yl[o] = l;
    }
}

// ---------------------------------------------------------------------------
// HMMA bf16x3-split GEMM — EXACT R11 config (best measured: 705us QKV).
// XOR-swizzled smem, single buffer, 2 CTAs/SM, CTA 128x128, 8 warps 4Mx2N.
// ---------------------------------------------------------------------------
#define TILE_B 16384                          // 128 rows * 128B
#define GEMM_SMEM_BYTES (4 * TILE_B)          // 65536 -> 2 CTAs/SM

__global__ __launch_bounds__(256, 2) void gemm_bf16x3(
    const __nv_bfloat16* __restrict__ Ah, const __nv_bfloat16* __restrict__ Al,
    const __nv_bfloat16* __restrict__ BhT, const __nv_bfloat16* __restrict__ BlT,
    const float* __restrict__ bias, float* __restrict__ Cc, int Ntot)
{
    extern __shared__ __align__(16) char smem[];
    char* tAh = smem;
    char* tAl = smem + TILE_B;
    char* tBh = smem + 2 * TILE_B;
    char* tBl = smem + 3 * TILE_B;

    const int tid = threadIdx.x;
    const int wid = tid >> 5, lane = tid & 31;
    const int wm = wid >> 1, wn = wid & 1;       // 4 x 2 warp grid
    const int quad = lane >> 2, tq = lane & 3;
    const int boff = tq * 4;                     // byte offset within 16B chunk
    const int m0 = blockIdx.y * 128, n0 = blockIdx.x * 128;

    // staging assignment: 4 groups of 64 threads, one 128x64-bf16 tile each
    const int grp = tid >> 6;
    const int gtid = tid & 63;
    const __nv_bfloat16* src =
        (grp == 0) ? Ah + (size_t)m0 * 512 :
        (grp == 1) ? Al + (size_t)m0 * 512 :
        (grp == 2) ? BhT + (size_t)n0 * 512 :
                     BlT + (size_t)n0 * 512;
    const uint32_t dt = smem_u32(smem) + grp * TILE_B;

    float acc[2][8][4] = {};   // [m-tile][n-tile][frag]

    for (int ch = 0; ch < 8; ++ch) {
        // stage chunk ch (swizzled)
#pragma unroll
        for (int i = 0; i < 16; ++i) {
            int idx = gtid + 64 * i;          // 0..1023
            int row = idx >> 3;               // 0..127
            int c16 = idx & 7;                // 16B chunk within the 128B row
            cp_async16(dt + row * 128 + ((c16 ^ (row & 7)) << 4),
                       src + (size_t)row * 512 + ch * 64 + c16 * 8);
        }
        asm volatile("cp.async.commit_group;" ::: "memory");
        asm volatile("cp.async.wait_group 0;" ::: "memory");
        __syncthreads();

        const int ra = wm * 32;               // A row base for this warp
        const int rb = wn * 64;               // B row base for this warp

#pragma unroll
        for (int ks = 0; ks < 4; ++ks) {
            const int c0_ = 2 * ks, c1_ = 2 * ks + 1;
            uint32_t ah[2][4], al[2][4];
#pragma unroll
            for (int mt = 0; mt < 2; ++mt) {
                const int r0 = ra + mt * 16 + quad, r1 = r0 + 8;
                ah[mt][0] = lds_sw(tAh, r0, c0_, boff);
                ah[mt][1] = lds_sw(tAh, r1, c0_, boff);
                ah[mt][2] = lds_sw(tAh, r0, c1_, boff);
                ah[mt][3] = lds_sw(tAh, r1, c1_, boff);
                al[mt][0] = lds_sw(tAl, r0, c0_, boff);
                al[mt][1] = lds_sw(tAl, r1, c0_, boff);
                al[mt][2] = lds_sw(tAl, r0, c1_, boff);
                al[mt][3] = lds_sw(tAl, r1, c1_, boff);
            }
#pragma unroll
            for (int nt = 0; nt < 8; ++nt) {
                const int nr = rb + nt * 8 + quad;
                uint32_t bh[2], bl[2];
                bh[0] = lds_sw(tBh, nr, c0_, boff);
                bh[1] = lds_sw(tBh, nr, c1_, boff);
                bl[0] = lds_sw(tBl, nr, c0_, boff);
                bl[1] = lds_sw(tBl, nr, c1_, boff);
#pragma unroll
                for (int mt = 0; mt < 2; ++mt) {
                    mma16816(acc[mt][nt], ah[mt], bh);
                    mma16816(acc[mt][nt], ah[mt], bl);
                    mma16816(acc[mt][nt], al[mt], bh);
                }
            }
        }
        __syncthreads();   // all warps done with this chunk before restaging
    }

    // epilogue
#pragma unroll
    for (int mt = 0; mt < 2; ++mt) {
        const int row = m0 + wm * 32 + mt * 16 + quad;
#pragma unroll
        for (int nt = 0; nt < 8; ++nt) {
            const int col = n0 + wn * 64 + nt * 8 + tq * 2;
            const float b0 = bias[col], b1 = bias[col + 1];
            float2 v0, v1;
            v0.x = acc[mt][nt][0] + b0; v0.y = acc[mt][nt][1] + b1;
            v1.x = acc[mt][nt][2] + b0; v1.y = acc[mt][nt][3] + b1;
            *(float2*)(Cc + (size_t)row * Ntot + col) = v0;
            *(float2*)(Cc + (size_t)(row + 8) * Ntot + col) = v1;
        }
    }
}

// ---------------------------------------------------------------------------
// Axial attention on tensor cores (bf16x3 split, inline conversion).
// Grid (bh=128, mode=2), 128 threads / 4 warps (2M x 2N), warp tile 32x32.
// Per chunk (one axial position, 64 channels): stage Q/K fp32 rows ->
// bf16 h/l smem tiles (144B row pitch, stride==4 mod 32 words -> conflict-
// free fragment LDS), then 3-product MMAs into fp32 acc.
// Epilogue: logits -> smem -> rowwise softmax -> out.
// ---------------------------------------------------------------------------
#define AXROW 144                              // bytes per tile row (64 bf16 + pad)
#define AXTILE (64 * AXROW)                    // 9216

__global__ __launch_bounds__(128, 2) void axial_mma(
    const float* __restrict__ qkv, float* __restrict__ outA,
    float* __restrict__ outB)
{
    __shared__ __align__(16) char axsm[4 * AXTILE];   // 36864
    char* tQh = axsm;
    char* tQl = axsm + AXTILE;
    char* tKh = axsm + 2 * AXTILE;
    char* tKl = axsm + 3 * AXTILE;

    const int bh = blockIdx.x;
    const int mode = blockIdx.y;
    const int b = bh >> 3, h = bh & 7;
    const float* qb = qkv + (size_t)b * NN * (3 * CC) + h * 64;

    const int tid = threadIdx.x;
    const int wid = tid >> 5, lane = tid & 31;
    const int wm = wid >> 1, wn = wid & 1;      // 2 x 2 warp grid
    const int quad = lane >> 2, tq = lane & 3;
    const int boff = tq * 4;

    // per-thread staging coordinates (fixed across chunks)
    int srow[8], soff[8];
#pragma unroll
    for (int j = 0; j < 8; ++j) {
        int idx = tid + 128 * j;                // 0..1023 float4 slots
        srow[j] = idx >> 4;                     // 0..63
        int c4 = idx & 15;                      // float4 within 64 channels
        soff[j] = srow[j] * AXROW + c4 * 8;
    }
    int scol4[8];
#pragma unroll
    for (int j = 0; j < 8; ++j) scol4[j] = ((tid + 128 * j) & 15) * 4;

    float acc[2][4][4] = {};   // [m-tile 16r][n-tile 8c][frag]

    for (int ch = 0; ch < 64; ++ch) {
        // stage: Q and K rows for axial position ch (64 rows x 64 ch each)
#pragma unroll
        for (int j = 0; j < 8; ++j) {
            int row = srow[j];
            int token = mode ? (ch * 64 + row) : (row * 64 + ch);
            const float* p = qb + (size_t)token * (3 * CC) + scol4[j];
            float4 q4 = *(const float4*)p;
            float4 k4 = *(const float4*)(p + CC);
            uint2 qh, ql, kh, kl;
            split4(q4, qh, ql);
            split4(k4, kh, kl);
            int off = soff[j];
            *(uint2*)(tQh + off) = qh;
            *(uint2*)(tQl + off) = ql;
            *(uint2*)(tKh + off) = kh;
            *(uint2*)(tKl + off) = kl;
        }
        __syncthreads();

        const int ra = wm * 32, rb = wn * 32;
#pragma unroll
        for (int ks = 0; ks < 4; ++ks) {
            const int koff = ks * 32;
            uint32_t ahf[2][4], alf[2][4];
#pragma unroll
            for (int mt = 0; mt < 2; ++mt) {
                const int r0 = ra + mt * 16 + quad, r1 = r0 + 8;
                ahf[mt][0] = *(const uint32_t*)(tQh + r0 * AXROW + koff + boff);
                ahf[mt][1] = *(const uint32_t*)(tQh + r1 * AXROW + koff + boff);
                ahf[mt][2] = *(const uint32_t*)(tQh + r0 * AXROW + koff + 16 + boff);
                ahf[mt][3] = *(const uint32_t*)(tQh + r1 * AXROW + koff + 16 + boff);
                alf[mt][0] = *(const uint32_t*)(tQl + r0 * AXROW + koff + boff);
                alf[mt][1] = *(const uint32_t*)(tQl + r1 * AXROW + koff + boff);
                alf[mt][2] = *(const uint32_t*)(tQl + r0 * AXROW + koff + 16 + boff);
                alf[mt][3] = *(const uint32_t*)(tQl + r1 * AXROW + koff + 16 + boff);
            }
#pragma unroll
            for (int nt = 0; nt < 4; ++nt) {
                const int nr = rb + nt * 8 + quad;
                uint32_t bhf[2], blf[2];
                bhf[0] = *(const uint32_t*)(tKh + nr * AXROW + koff + boff);
                bhf[1] = *(const uint32_t*)(tKh + nr * AXROW + koff + 16 + boff);
                blf[0] = *(const uint32_t*)(tKl + nr * AXROW + koff + boff);
                blf[1] = *(const uint32_t*)(tKl + nr * AXROW + koff + 16 + boff);
#pragma unroll
                for (int mt = 0; mt < 2; ++mt) {
                    mma16816(acc[mt][nt], ahf[mt], bhf);
                    mma16816(acc[mt][nt], ahf[mt], blf);
                    mma16816(acc[mt][nt], alf[mt], bhf);
                }
            }
        }
        __syncthreads();
    }

    // logits -> smem (reuse tile space), fp32, row stride 272B (68 floats)
    float* S = (float*)axsm;
#pragma unroll
    for (int mt = 0; mt < 2; ++mt) {
        const int row = wm * 32 + mt * 16 + quad;
#pragma unroll
        for (int nt = 0; nt < 4; ++nt) {
            const int col = wn * 32 + nt * 8 + tq * 2;
            float2 v0, v1;
            v0.x = acc[mt][nt][0] * kSCALE; v0.y = acc[mt][nt][1] * kSCALE;
            v1.x = acc[mt][nt][2] * kSCALE; v1.y = acc[mt][nt][3] * kSCALE;
            *(float2*)(S + row * 68 + col) = v0;
            *(float2*)(S + (row + 8) * 68 + col) = v1;
        }
    }
    __syncthreads();

    // rowwise softmax (4 warps, 16 rows each)
    float* ob = (mode ? outB : outA) + (size_t)bh * 4096;
    for (int r = wid; r < 64; r += 4) {
        float v0 = S[r * 68 + lane], v1 = S[r * 68 + lane + 32];
        float m = fmaxf(v0, v1);
#pragma unroll
        for (int o = 16; o > 0; o >>= 1)
            m = fmaxf(m, __shfl_xor_sync(0xffffffffu, m, o));
        float e0 = __expf(v0 - m), e1 = __expf(v1 - m);
        float s = e0 + e1;
#pragma unroll
        for (int o = 16; o > 0; o >>= 1)
            s += __shfl_xor_sync(0xffffffffu, s, o);
        float inv = 1.0f / s;
        ob[r * 64 + lane] = e0 * inv;
        ob[r * 64 + lane + 32] = e1 * inv;
    }
}

// ---------------------------------------------------------------------------
// Transpose V: qkv v-part [token, h*64+c] -> Vt[bh][c][t][w]
// ---------------------------------------------------------------------------
__global__ __launch_bounds__(256) void transpose_v(
    const float* __restrict__ qkv, float* __restrict__ Vt)
{
    const int t = blockIdx.x;
    const int bh = blockIdx.y;
    const int b = bh >> 3, h = bh & 7;
    __shared__ float tile[64][65];
    const int tid = threadIdx.x;
    const int tx = tid & 15, ty = tid >> 4;

    const float* vbase = qkv + (size_t)b * NN * (3 * CC) + 2 * CC + h * 64;
#pragma unroll
    for (int p = 0; p < 4; ++p) {
        int w = ty + p * 16;
        float4 v4 = *(const float4*)(vbase + (size_t)(t * 64 + w) * (3 * CC) + tx * 4);
        tile[w][tx * 4 + 0] = v4.x; tile[w][tx * 4 + 1] = v4.y;
        tile[w][tx * 4 + 2] = v4.z; tile[w][tx * 4 + 3] = v4.w;
    }
    __syncthreads();

    float* obase = Vt + (size_t)bh * 64 * 4096 + t * 64;
#pragma unroll
    for (int p = 0; p < 4; ++p) {
        int c = ty + p * 16;
        float4 o;
        o.x = tile[tx * 4 + 0][c];
        o.y = tile[tx * 4 + 1][c];
        o.z = tile[tx * 4 + 2][c];
        o.w = tile[tx * 4 + 3][c];
        *(float4*)(obase + (size_t)c * 4096 + tx * 4) = o;
    }
}

// ---------------------------------------------------------------------------
// Coupled combine: one block per (c, bh).
// ---------------------------------------------------------------------------
__global__ __launch_bounds__(256) void combine_kernel(
    const float* __restrict__ Abuf, const float* __restrict__ Bmbuf,
    const float* __restrict__ Vt, float* __restrict__ attnT)
{
    extern __shared__ float sm[];
    float (*As_)[65] = reinterpret_cast<float (*)[65]>(sm);
    float (*Bs_)[65] = reinterpret_cast<float (*)[65]>(sm + 64 * 65);
    float (*Vs)[65]  = reinterpret_cast<float (*)[65]>(sm + 2 * 64 * 65);
    float (*Ts)[65]  = reinterpret_cast<float (*)[65]>(sm + 3 * 64 * 65);

    const int c = blockIdx.x;
    const int bh = blockIdx.y;
    const int tid = threadIdx.x;
    const int tx = tid & 15, ty = tid >> 4;

    const float* ab = Abuf + (size_t)bh * 4096;
    const float* bb = Bmbuf + (size_t)bh * 4096;
    const float* vb = Vt + ((size_t)bh * 64 + c) * 4096;

#pragma unroll
    for (int p = 0; p < 4; ++p) {
        int row = ty + p * 16;
        float4 a4 = *(const float4*)(ab + row * 64 + tx * 4);
        float4 b4 = *(const float4*)(bb + row * 64 + tx * 4);
        float4 v4 = *(const float4*)(vb + row * 64 + tx * 4);
        As_[row][tx * 4 + 0] = a4.x; As_[row][tx * 4 + 1] = a4.y;
        As_[row][tx * 4 + 2] = a4.z; As_[row][tx * 4 + 3] = a4.w;
        Bs_[row][tx * 4 + 0] = b4.x; Bs_[row][tx * 4 + 1] = b4.y;
        Bs_[row][tx * 4 + 2] = b4.z; Bs_[row][tx * 4 + 3] = b4.w;
        Vs[row][tx * 4 + 0] = v4.x; Vs[row][tx * 4 + 1] = v4.y;
        Vs[row][tx * 4 + 2] = v4.z; Vs[row][tx * 4 + 3] = v4.w;
    }
    __syncthreads();

    {
        float acc[4][4] = {};
#pragma unroll 16
        for (int w = 0; w < 64; ++w) {
            float vf[4], bf[4];
#pragma unroll
            for (int i = 0; i < 4; ++i) vf[i] = Vs[ty * 4 + i][w];
#pragma unroll
            for (int j = 0; j < 4; ++j) bf[j] = Bs_[tx * 4 + j][w];
#pragma unroll
            for (int i = 0; i < 4; ++i)
#pragma unroll
                for (int j = 0; j < 4; ++j)
                    acc[i][j] += vf[i] * bf[j];
        }
#pragma unroll
        for (int i = 0; i < 4; ++i)
#pragma unroll
            for (int j = 0; j < 4; ++j)
                Ts[ty * 4 + i][tx * 4 + j] = acc[i][j];
    }
    __syncthreads();

    float acc[4][4] = {};
#pragma unroll 16
    for (int j = 0; j < 64; ++j) {
        float af[4], tf[4];
#pragma unroll
        for (int i = 0; i < 4; ++i) af[i] = As_[ty * 4 + i][j];
#pragma unroll
        for (int jj = 0; jj < 4; ++jj) tf[jj] = Ts[j][tx * 4 + jj];
#pragma unroll
        for (int i = 0; i < 4; ++i)
#pragma unroll
            for (int jj = 0; jj < 4; ++jj)
                acc[i][jj] += af[i] * tf[jj];
    }

    float* ob = attnT + ((size_t)bh * 64 + c) * 4096;
#pragma unroll
    for (int i = 0; i < 4; ++i) {
        float4 o;
        o.x = acc[i][0]; o.y = acc[i][1]; o.z = acc[i][2]; o.w = acc[i][3];
        *(float4*)(ob + (ty * 4 + i) * 64 + tx * 4) = o;
    }
}

// ---------------------------------------------------------------------------
extern "C" void kernel_launch(void* const* d_in, const int* in_sizes, int n_in,
                              void* d_out, int out_size)
{
    const float* x     = (const float*)d_in[0];
    const float* Wqkv  = (const float*)d_in[1];
    const float* bqkv  = (const float*)d_in[2];
    const float* Wproj = (const float*)d_in[3];
    const float* bproj = (const float*)d_in[4];
    float* out = (float*)d_out;

    float *qkv, *Ab, *Bmb, *Vt, *attnT;
    __nv_bfloat16 *Xh, *Xl, *WqTh, *WqTl, *WpTh, *WpTl;
    cudaGetSymbolAddress((void**)&qkv, g_qkv);
    cudaGetSymbolAddress((void**)&Ab, g_A);
    cudaGetSymbolAddress((void**)&Bmb, g_Bm);
    cudaGetSymbolAddress((void**)&Vt, g_Vt);
    cudaGetSymbolAddress((void**)&attnT, g_attnT);
    cudaGetSymbolAddress((void**)&Xh, g_Xh);
    cudaGetSymbolAddress((void**)&Xl, g_Xl);
    cudaGetSymbolAddress((void**)&WqTh, g_WqTh);
    cudaGetSymbolAddress((void**)&WqTl, g_WqTl);
    cudaGetSymbolAddress((void**)&WpTh, g_WpTh);
    cudaGetSymbolAddress((void**)&WpTl, g_WpTl);

    // host-side attribute sets (capture-safe; proven)
    cudaFuncSetAttribute(gemm_bf16x3, cudaFuncAttributeMaxDynamicSharedMemorySize,
                         GEMM_SMEM_BYTES);
    cudaFuncSetAttribute(combine_kernel, cudaFuncAttributeMaxDynamicSharedMemorySize,
                         4 * 64 * 65 * sizeof(float));

    // 0. split inputs to bf16 hi/lo
    split_f32<<<(BB * NN * CC / 4 + 255) / 256, 256>>>(x, Xh, Xl, BB * NN * CC / 4);
    split_transpose_w<<<dim3(1536 / 32, 512 / 32), dim3(32, 8)>>>(Wqkv, WqTh, WqTl, 1536);
    split_transpose_w<<<dim3(512 / 32, 512 / 32), dim3(32, 8)>>>(Wproj, WpTh, WpTl, 512);

    // 1. QKV projection on tensor cores: [65536,512] x [512,1536]
    gemm_bf16x3<<<dim3(1536 / 128, (BB * NN) / 128), 256, GEMM_SMEM_BYTES>>>(
        Xh, Xl, WqTh, WqTl, bqkv, qkv, 1536);

    // 2+3. axial attentions (row + col) on tensor cores
    axial_mma<<<dim3(BB * HH, 2), 128>>>(qkv, Ab, Bmb);

    // 4. transpose V to channel-major
    transpose_v<<<dim3(64, BB * HH), 256>>>(qkv, Vt);

    // 5. coupled combine -> attnT [B, C, N]
    combine_kernel<<<dim3(64, BB * HH), 256, 4 * 64 * 65 * sizeof(float)>>>(Ab, Bmb, Vt, attnT);

    // 6. split+transpose attn output to token-major bf16 (reuse Xh/Xl)
    split_transpose_attn<<<dim3(NN / 32, CC / 32, BB), dim3(32, 8)>>>(attnT, Xh, Xl);

    // 7. projection on tensor cores: [65536,512] x [512,512]
    gemm_bf16x3<<<dim3(512 / 128, (BB * NN) / 128), 256, GEMM_SMEM_BYTES>>>(
        Xh, Xl, WpTh, WpTl, bproj, out, 512);
}